// round 1
// baseline (speedup 1.0000x reference)
#include <cuda_runtime.h>
#include <cuda_bf16.h>
#include <math.h>

// Problem constants (fixed by the reference)
#define BSZ     16
#define DIM     4096
#define NH      32
#define NKV     8
#define HD      128
#define SEQ     4096
#define POS     4095
#define NCHUNK  8
#define CHUNK   512   // SEQ / NCHUNK

// ---------------- scratch (static __device__, no allocation) ----------------
__device__ float g_xt[DIM * BSZ];                       // x transposed [d][b]
__device__ float g_q[BSZ * NH * HD];                    // [b][h][d]
__device__ float g_k[BSZ * NKV * HD];                   // [b][kvh][d]
__device__ float g_v[BSZ * NKV * HD];                   // [b][kvh][d]
__device__ float g_attn_t[DIM * BSZ];                   // attention out transposed [e][b]
__device__ float g_Opart[BSZ * NKV * NCHUNK * 4 * HD];  // [b][kvh][chunk][hloc][d]
__device__ float g_m[BSZ * NKV * NCHUNK * 4];
__device__ float g_l[BSZ * NKV * NCHUNK * 4];

// ---------------- x transpose: x[b][d] -> g_xt[d][b] ----------------
__global__ void __launch_bounds__(256) transpose_x_kernel(const float* __restrict__ x)
{
    int gid = blockIdx.x * 256 + threadIdx.x;   // gid = d*16 + b
    int d = gid >> 4;
    int b = gid & 15;
    g_xt[gid] = x[b * DIM + d];
}

// ---------------- skinny GEMM: out[b][row] = sum_d W[row][d] * xt[d][b] ----------------
// W: [nrows][4096] row-major. xt: [4096][16]. out: [16][nrows].
// Block: 256 threads, BM=32 rows, BN=16 (all batches), BK=64.
__global__ void __launch_bounds__(256) gemm16_kernel(const float* __restrict__ W,
                                                     const float* __restrict__ xt,
                                                     float* __restrict__ out,
                                                     int nrows)
{
    __shared__ float  ws[32][68];       // padded: bank-conflict-free, 16B-aligned rows
    __shared__ float2 xs[64][8];        // [k][batch-pair]

    int tid = threadIdx.x;
    int row0 = blockIdx.x * 32;
    int ty = tid >> 3;                  // 0..31 -> m
    int tx = tid & 7;                   // 0..7  -> batch pair (2*tx, 2*tx+1)

    float acc0 = 0.f, acc1 = 0.f;

    for (int kb = 0; kb < DIM; kb += 64) {
        // stage W tile 32x64 (512 float4, 2 per thread), coalesced
        #pragma unroll
        for (int i = 0; i < 2; i++) {
            int f  = tid * 2 + i;       // 0..511
            int m  = f >> 4;            // 16 float4 per row
            int kf = f & 15;
            const float4 w4 = *reinterpret_cast<const float4*>(
                &W[(size_t)(row0 + m) * DIM + kb + kf * 4]);
            *reinterpret_cast<float4*>(&ws[m][kf * 4]) = w4;
        }
        // stage x tile 64x16 (256 float4, 1 per thread), coalesced
        {
            int k  = tid >> 2;
            int b4 = tid & 3;
            const float4 x4 = *reinterpret_cast<const float4*>(&xt[(kb + k) * BSZ + b4 * 4]);
            xs[k][b4 * 2 + 0] = make_float2(x4.x, x4.y);
            xs[k][b4 * 2 + 1] = make_float2(x4.z, x4.w);
        }
        __syncthreads();

        #pragma unroll
        for (int k = 0; k < 64; k++) {
            float  w  = ws[ty][k];      // broadcast across tx
            float2 xv = xs[k][tx];
            acc0 = fmaf(w, xv.x, acc0);
            acc1 = fmaf(w, xv.y, acc1);
        }
        __syncthreads();
    }

    int row = row0 + ty;
    out[(size_t)(2 * tx)     * nrows + row] = acc0;
    out[(size_t)(2 * tx + 1) * nrows + row] = acc1;
}

// ---------------- RoPE (+ 1/sqrt(HD) scale folded into q) ----------------
// Pairs: q has 16*32*64 = 32768, k has 16*8*64 = 8192. Total 40960.
__global__ void __launch_bounds__(256) rope_kernel(const float* __restrict__ fcos,
                                                   const float* __restrict__ fsin)
{
    int id = blockIdx.x * 256 + threadIdx.x;
    const float scale = 0.08838834764831845f;   // 1/sqrt(128)
    if (id < BSZ * NH * (HD / 2)) {
        int i = id & 63;
        float c = fcos[i], s = fsin[i];
        float a  = g_q[2 * id];
        float bb = g_q[2 * id + 1];
        g_q[2 * id]     = (a * c - bb * s) * scale;
        g_q[2 * id + 1] = (a * s + bb * c) * scale;
    } else {
        int kid = id - BSZ * NH * (HD / 2);
        if (kid < BSZ * NKV * (HD / 2)) {
            int i = kid & 63;
            float c = fcos[i], s = fsin[i];
            float a  = g_k[2 * kid];
            float bb = g_k[2 * kid + 1];
            g_k[2 * kid]     = a * c - bb * s;
            g_k[2 * kid + 1] = a * s + bb * c;
        }
    }
}

// ---------------- flash-decoding partial attention ----------------
// grid (chunk=8, kvh=8, b=16), 256 threads = 8 warps. Each warp: 64 keys.
// 4 GQA q-heads per kv-head handled together.
__global__ void __launch_bounds__(256) attn_partial_kernel(const float* __restrict__ cache_k,
                                                           const float* __restrict__ cache_v)
{
    int chunk = blockIdx.x;
    int kvh   = blockIdx.y;
    int b     = blockIdx.z;
    int tid   = threadIdx.x;
    int warp  = tid >> 5;
    int lane  = tid & 31;

    __shared__ float  sc[4][CHUNK];          // scores then probs  (8 KB)
    __shared__ float  wm[8][4];
    __shared__ float  mfin[4];
    __shared__ float  lfin[4];
    __shared__ float4 ored[8][4][32];        // per-warp PV partials (16 KB)

    if (tid < 4) lfin[tid] = 0.f;

    // q for the 4 heads of this kv group (pre-scaled by 1/sqrt(HD))
    float4 qv[4];
    #pragma unroll
    for (int h = 0; h < 4; h++)
        qv[h] = *reinterpret_cast<const float4*>(
            &g_q[((b * NH) + kvh * 4 + h) * HD + lane * 4]);

    float m0 = -1e30f, m1 = -1e30f, m2 = -1e30f, m3 = -1e30f;
    int key0 = chunk * CHUNK + warp * 64;

    // ---- phase 1: QK scores ----
    #pragma unroll 2
    for (int i = 0; i < 64; i++) {
        int key = key0 + i;
        const float* krow = (key == POS)
            ? &g_k[(b * NKV + kvh) * HD]
            : &cache_k[(((size_t)b * SEQ + key) * NKV + kvh) * HD];
        float4 kv = *reinterpret_cast<const float4*>(&krow[lane * 4]);

        float s0 = qv[0].x * kv.x + qv[0].y * kv.y + qv[0].z * kv.z + qv[0].w * kv.w;
        float s1 = qv[1].x * kv.x + qv[1].y * kv.y + qv[1].z * kv.z + qv[1].w * kv.w;
        float s2 = qv[2].x * kv.x + qv[2].y * kv.y + qv[2].z * kv.z + qv[2].w * kv.w;
        float s3 = qv[3].x * kv.x + qv[3].y * kv.y + qv[3].z * kv.z + qv[3].w * kv.w;
        #pragma unroll
        for (int off = 16; off; off >>= 1) {
            s0 += __shfl_xor_sync(0xffffffffu, s0, off);
            s1 += __shfl_xor_sync(0xffffffffu, s1, off);
            s2 += __shfl_xor_sync(0xffffffffu, s2, off);
            s3 += __shfl_xor_sync(0xffffffffu, s3, off);
        }
        m0 = fmaxf(m0, s0); m1 = fmaxf(m1, s1);
        m2 = fmaxf(m2, s2); m3 = fmaxf(m3, s3);
        if (lane < 4) {
            float sv = (lane == 0) ? s0 : (lane == 1) ? s1 : (lane == 2) ? s2 : s3;
            sc[lane][warp * 64 + i] = sv;
        }
    }
    if (lane < 4)
        wm[warp][lane] = (lane == 0) ? m0 : (lane == 1) ? m1 : (lane == 2) ? m2 : m3;
    __syncthreads();

    if (tid < 4) {
        float m = wm[0][tid];
        #pragma unroll
        for (int w = 1; w < 8; w++) m = fmaxf(m, wm[w][tid]);
        mfin[tid] = m;
    }
    __syncthreads();

    // ---- phase 2: softmax numerator + l ----
    {
        int h = tid >> 6;                 // 64 threads (2 warps) per head
        float m = mfin[h];
        float lsum = 0.f;
        #pragma unroll
        for (int j = 0; j < 8; j++) {
            int kk = (tid & 63) * 8 + j;
            float p = __expf(sc[h][kk] - m);
            sc[h][kk] = p;
            lsum += p;
        }
        #pragma unroll
        for (int off = 16; off; off >>= 1)
            lsum += __shfl_xor_sync(0xffffffffu, lsum, off);
        if (lane == 0) atomicAdd(&lfin[h], lsum);
    }
    __syncthreads();

    // ---- phase 3: P @ V ----
    float4 a0 = make_float4(0, 0, 0, 0), a1 = a0, a2 = a0, a3 = a0;
    #pragma unroll 2
    for (int i = 0; i < 64; i++) {
        int key = key0 + i;
        const float* vrow = (key == POS)
            ? &g_v[(b * NKV + kvh) * HD]
            : &cache_v[(((size_t)b * SEQ + key) * NKV + kvh) * HD];
        float4 vv = *reinterpret_cast<const float4*>(&vrow[lane * 4]);
        int kl = warp * 64 + i;
        float p0 = sc[0][kl], p1 = sc[1][kl], p2 = sc[2][kl], p3 = sc[3][kl];
        a0.x += p0 * vv.x; a0.y += p0 * vv.y; a0.z += p0 * vv.z; a0.w += p0 * vv.w;
        a1.x += p1 * vv.x; a1.y += p1 * vv.y; a1.z += p1 * vv.z; a1.w += p1 * vv.w;
        a2.x += p2 * vv.x; a2.y += p2 * vv.y; a2.z += p2 * vv.z; a2.w += p2 * vv.w;
        a3.x += p3 * vv.x; a3.y += p3 * vv.y; a3.z += p3 * vv.z; a3.w += p3 * vv.w;
    }
    ored[warp][0][lane] = a0;
    ored[warp][1][lane] = a1;
    ored[warp][2][lane] = a2;
    ored[warp][3][lane] = a3;
    __syncthreads();

    // cross-warp reduce: 512 outputs (4 heads x 128 dims), 2 per thread
    const float* of = reinterpret_cast<const float*>(ored);
    int pbase = ((b * NKV + kvh) * NCHUNK + chunk) * 4;
    #pragma unroll
    for (int r = 0; r < 2; r++) {
        int o  = tid + r * 256;
        int hh = o >> 7;
        int d  = o & 127;
        float sum = 0.f;
        #pragma unroll
        for (int w = 0; w < 8; w++)
            sum += of[(w * 4 + hh) * HD + d];
        g_Opart[(size_t)(pbase + hh) * HD + d] = sum;
    }
    if (tid < 4) {
        g_m[pbase + tid] = mfin[tid];
        g_l[pbase + tid] = lfin[tid];
    }
}

// ---------------- split-softmax combine -> g_attn_t[e][b] ----------------
__global__ void __launch_bounds__(128) combine_kernel()
{
    int kvh = blockIdx.x;
    int b   = blockIdx.y;
    int d   = threadIdx.x;

    #pragma unroll
    for (int h = 0; h < 4; h++) {
        int base = ((b * NKV + kvh) * NCHUNK) * 4 + h;   // + c*4
        float mstar = -1e30f;
        #pragma unroll
        for (int c = 0; c < NCHUNK; c++) mstar = fmaxf(mstar, g_m[base + c * 4]);
        float num = 0.f, den = 0.f;
        #pragma unroll
        for (int c = 0; c < NCHUNK; c++) {
            float w = __expf(g_m[base + c * 4] - mstar);
            den += g_l[base + c * 4] * w;
            num += g_Opart[(size_t)(base + c * 4) * HD + d] * w;
        }
        int e = (kvh * 4 + h) * HD + d;
        g_attn_t[e * BSZ + b] = num / den;
    }
}

// ---------------- launcher ----------------
extern "C" void kernel_launch(void* const* d_in, const int* in_sizes, int n_in,
                              void* d_out, int out_size)
{
    (void)in_sizes; (void)n_in; (void)out_size;
    const float* x  = (const float*)d_in[0];
    const float* wq = (const float*)d_in[1];
    const float* wk = (const float*)d_in[2];
    const float* wv = (const float*)d_in[3];
    const float* wo = (const float*)d_in[4];
    const float* ck = (const float*)d_in[5];
    const float* cv = (const float*)d_in[6];
    const float* fc = (const float*)d_in[7];
    const float* fs = (const float*)d_in[8];
    float* out = (float*)d_out;

    void *p_xt, *p_q, *p_k, *p_v, *p_at;
    cudaGetSymbolAddress(&p_xt, g_xt);
    cudaGetSymbolAddress(&p_q,  g_q);
    cudaGetSymbolAddress(&p_k,  g_k);
    cudaGetSymbolAddress(&p_v,  g_v);
    cudaGetSymbolAddress(&p_at, g_attn_t);

    transpose_x_kernel<<<256, 256>>>(x);
    gemm16_kernel<<<128, 256>>>(wq, (const float*)p_xt, (float*)p_q, DIM);
    gemm16_kernel<<< 32, 256>>>(wk, (const float*)p_xt, (float*)p_k, NKV * HD);
    gemm16_kernel<<< 32, 256>>>(wv, (const float*)p_xt, (float*)p_v, NKV * HD);
    rope_kernel<<<160, 256>>>(fc, fs);
    attn_partial_kernel<<<dim3(NCHUNK, NKV, BSZ), 256>>>(ck, cv);
    combine_kernel<<<dim3(NKV, BSZ), 128>>>();
    gemm16_kernel<<<128, 256>>>(wo, (const float*)p_at, out, DIM);
}

// round 3
// speedup vs baseline: 1.8052x; 1.8052x over previous
#include <cuda_runtime.h>
#include <cuda_bf16.h>
#include <math.h>

// Problem constants (fixed by the reference)
#define BSZ     16
#define DIM     4096
#define NH      32
#define NKV     8
#define HD      128
#define SEQ     4096
#define POS     4095
#define NCHUNK  8
#define CHUNK   512   // SEQ / NCHUNK

// GEMM tiling
#define KC      256                    // k per staged chunk
#define NKCH    (DIM / KC)             // 16 chunks

#define KVROWS  (NKV * HD)             // 1024 rows in wk / wv

// ---------------- scratch (static __device__, no allocation) ----------------
__device__ float g_xt2[8 * DIM * 2];                    // x pair-major [pair][d][2]
__device__ float g_q[BSZ * NH * HD];                    // [b][h][d]
__device__ float g_k[BSZ * KVROWS];                     // [b][kvh][d]
__device__ float g_v[BSZ * KVROWS];                     // [b][kvh][d]
__device__ float g_at2[8 * DIM * 2];                    // attn out pair-major [pair][e][2]
__device__ float g_Opart[BSZ * NKV * NCHUNK * 4 * HD];  // [b][kvh][chunk][hloc][d]
__device__ float g_m[BSZ * NKV * NCHUNK * 4];
__device__ float g_l[BSZ * NKV * NCHUNK * 4];

// ---------------- f32x2 helpers (sm_103a packed fp32) ----------------
__device__ __forceinline__ unsigned long long pack2(float a, float b) {
    unsigned long long r;
    asm("mov.b64 %0, {%1, %2};" : "=l"(r) : "f"(a), "f"(b));
    return r;
}
__device__ __forceinline__ void unpack2(unsigned long long v, float& a, float& b) {
    asm("mov.b64 {%0, %1}, %2;" : "=f"(a), "=f"(b) : "l"(v));
}
__device__ __forceinline__ unsigned long long fma2(unsigned long long a,
                                                   unsigned long long b,
                                                   unsigned long long c) {
    unsigned long long d;
    asm("fma.rn.f32x2 %0, %1, %2, %3;" : "=l"(d) : "l"(a), "l"(b), "l"(c));
    return d;
}
__device__ __forceinline__ unsigned long long add2(unsigned long long a,
                                                   unsigned long long b) {
    unsigned long long d;
    asm("add.rn.f32x2 %0, %1, %2;" : "=l"(d) : "l"(a), "l"(b));
    return d;
}

// ---------------- cp.async helpers ----------------
__device__ __forceinline__ void cp_async16(void* smem, const void* gmem) {
    unsigned sa = (unsigned)__cvta_generic_to_shared(smem);
    asm volatile("cp.async.ca.shared.global [%0], [%1], 16;" :: "r"(sa), "l"(gmem) : "memory");
}
__device__ __forceinline__ void cp_commit() {
    asm volatile("cp.async.commit_group;" ::: "memory");
}

// ---------------- x transpose: x[b][d] -> g_xt2 pair-major ----------------
__global__ void __launch_bounds__(256) transpose_x_kernel(const float* __restrict__ x)
{
    int gid = blockIdx.x * 256 + threadIdx.x;   // gid = b*4096 + d
    int b = gid >> 12;
    int d = gid & 4095;
    g_xt2[(b >> 1) * (DIM * 2) + d * 2 + (b & 1)] = x[gid];
}

// ---------------- GEMM core ----------------
// Per block: 8 warps x 4 rows = 32 rows, all 16 batches, full K=4096.
// Lanes spread along k (stride 1, coalesced LDG.32). x staged pair-major in
// smem (double-buffered cp.async). Accumulators are f32x2-packed batch pairs.
// Cross-lane k-reduction by f32x2 butterfly at the end.
__device__ __forceinline__ void gemm_core(const float* __restrict__ W,   // warp's row0, [4][DIM]
                                          const float* __restrict__ xt2, // pair-major [8][DIM][2]
                                          float* __restrict__ dst,       // [16][dsz]
                                          int dsz, int drow)
{
    __shared__ __align__(16) float xs[2][8][KC][2];   // 32 KB

    const int tid  = threadIdx.x;
    const int lane = tid & 31;

    unsigned long long acc[32];
    #pragma unroll
    for (int i = 0; i < 32; i++) acc[i] = 0ULL;

    // stage chunk 0
    #pragma unroll
    for (int t = 0; t < 4; t++) {
        int i = tid + t * 256;
        int p = i >> 7;          // plane (batch pair)
        int f = i & 127;         // float4 within plane-chunk
        cp_async16(&xs[0][p][0][0] + f * 4, xt2 + p * (DIM * 2) + f * 4);
    }
    cp_commit();

    const float* w0 = W;
    const float* w1 = W + DIM;
    const float* w2 = W + 2 * DIM;
    const float* w3 = W + 3 * DIM;

    // prefetch W for chunk 0, step 0
    float wc0 = w0[lane], wc1 = w1[lane], wc2 = w2[lane], wc3 = w3[lane];

    for (int c = 0; c < NKCH; c++) {
        if (c < NKCH - 1) {
            // stage next chunk into the other buffer
            #pragma unroll
            for (int t = 0; t < 4; t++) {
                int i = tid + t * 256;
                int p = i >> 7;
                int f = i & 127;
                cp_async16(&xs[(c + 1) & 1][p][0][0] + f * 4,
                           xt2 + p * (DIM * 2) + (c + 1) * (KC * 2) + f * 4);
            }
            cp_commit();
            asm volatile("cp.async.wait_group 1;" ::: "memory");
        } else {
            asm volatile("cp.async.wait_group 0;" ::: "memory");
        }
        __syncthreads();

        const float (*xb)[KC][2] = xs[c & 1];

        #pragma unroll
        for (int s = 0; s < 8; s++) {
            int kl = s * 32 + lane;                      // k within chunk
            int kn = (c * KC + kl + 32) & (DIM - 1);     // next-step k (wrap-safe)

            // prefetch next step's W
            float wn0 = w0[kn], wn1 = w1[kn], wn2 = w2[kn], wn3 = w3[kn];

            // x pairs for this k (shared across the 4 rows)
            unsigned long long xp[8];
            #pragma unroll
            for (int p = 0; p < 8; p++)
                xp[p] = *reinterpret_cast<const unsigned long long*>(&xb[p][kl][0]);

            unsigned long long wv;
            wv = pack2(wc0, wc0);
            #pragma unroll
            for (int p = 0; p < 8; p++) acc[0 * 8 + p] = fma2(wv, xp[p], acc[0 * 8 + p]);
            wv = pack2(wc1, wc1);
            #pragma unroll
            for (int p = 0; p < 8; p++) acc[1 * 8 + p] = fma2(wv, xp[p], acc[1 * 8 + p]);
            wv = pack2(wc2, wc2);
            #pragma unroll
            for (int p = 0; p < 8; p++) acc[2 * 8 + p] = fma2(wv, xp[p], acc[2 * 8 + p]);
            wv = pack2(wc3, wc3);
            #pragma unroll
            for (int p = 0; p < 8; p++) acc[3 * 8 + p] = fma2(wv, xp[p], acc[3 * 8 + p]);

            wc0 = wn0; wc1 = wn1; wc2 = wn2; wc3 = wn3;
        }
        __syncthreads();
    }

    // butterfly reduce across lanes (k partials)
    #pragma unroll
    for (int off = 16; off; off >>= 1) {
        #pragma unroll
        for (int i = 0; i < 32; i++)
            acc[i] = add2(acc[i], __shfl_xor_sync(0xffffffffu, acc[i], off));
    }

    if (lane < 16) {
        int p = lane >> 1, h = lane & 1;
        #pragma unroll
        for (int r = 0; r < 4; r++) {
            float lo, hi;
            unpack2(acc[r * 8 + p], lo, hi);
            dst[(size_t)lane * dsz + drow + r] = h ? hi : lo;
        }
    }
}

// Fused QKV GEMM over 6144 rows:
//   rows 0..4095   -> wq  (g_q,  dsz 4096)
//   rows 4096..5119 -> wk (g_k,  dsz 1024)
//   rows 5120..6143 -> wv (g_v,  dsz 1024)
__global__ void __launch_bounds__(256) qkv_gemm_kernel(const float* __restrict__ wq,
                                                       const float* __restrict__ wk,
                                                       const float* __restrict__ wv)
{
    int row0 = blockIdx.x * 32 + (threadIdx.x >> 5) * 4;
    const float* W; float* dst; int dsz, drow;
    if (row0 < 4096) {
        W = wq + (size_t)row0 * DIM;           dst = g_q; dsz = 4096;   drow = row0;
    } else if (row0 < 4096 + KVROWS) {
        W = wk + (size_t)(row0 - 4096) * DIM;  dst = g_k; dsz = KVROWS; drow = row0 - 4096;
    } else {
        W = wv + (size_t)(row0 - 4096 - KVROWS) * DIM;
        dst = g_v; dsz = KVROWS; drow = row0 - 4096 - KVROWS;
    }
    gemm_core(W, g_xt2, dst, dsz, drow);
}

__global__ void __launch_bounds__(256) wo_gemm_kernel(const float* __restrict__ wo,
                                                      float* __restrict__ out)
{
    int row0 = blockIdx.x * 32 + (threadIdx.x >> 5) * 4;
    gemm_core(wo + (size_t)row0 * DIM, g_at2, out, 4096, row0);
}

// ---------------- RoPE (+ 1/sqrt(HD) scale folded into q) ----------------
// Pairs: q has 16*32*64 = 32768, k has 16*8*64 = 8192. Total 40960.
__global__ void __launch_bounds__(256) rope_kernel(const float* __restrict__ fcos,
                                                   const float* __restrict__ fsin)
{
    int id = blockIdx.x * 256 + threadIdx.x;
    const float scale = 0.08838834764831845f;   // 1/sqrt(128)
    if (id < BSZ * NH * (HD / 2)) {
        int i = id & 63;
        float c = fcos[i], s = fsin[i];
        float a  = g_q[2 * id];
        float bb = g_q[2 * id + 1];
        g_q[2 * id]     = (a * c - bb * s) * scale;
        g_q[2 * id + 1] = (a * s + bb * c) * scale;
    } else {
        int kid = id - BSZ * NH * (HD / 2);
        if (kid < BSZ * NKV * (HD / 2)) {
            int i = kid & 63;
            float c = fcos[i], s = fsin[i];
            float a  = g_k[2 * kid];
            float bb = g_k[2 * kid + 1];
            g_k[2 * kid]     = a * c - bb * s;
            g_k[2 * kid + 1] = a * s + bb * c;
        }
    }
}

// ---------------- flash-decoding partial attention ----------------
// grid (chunk=8, kvh=8, b=16), 256 threads = 8 warps. Each warp: 64 keys.
__global__ void __launch_bounds__(256) attn_partial_kernel(const float* __restrict__ cache_k,
                                                           const float* __restrict__ cache_v)
{
    int chunk = blockIdx.x;
    int kvh   = blockIdx.y;
    int b     = blockIdx.z;
    int tid   = threadIdx.x;
    int warp  = tid >> 5;
    int lane  = tid & 31;

    __shared__ float  sc[4][CHUNK];          // scores then probs  (8 KB)
    __shared__ float  wm[8][4];
    __shared__ float  mfin[4];
    __shared__ float  lfin[4];
    __shared__ float4 ored[8][4][32];        // per-warp PV partials (16 KB)

    if (tid < 4) lfin[tid] = 0.f;

    float4 qv[4];
    #pragma unroll
    for (int h = 0; h < 4; h++)
        qv[h] = *reinterpret_cast<const float4*>(
            &g_q[((b * NH) + kvh * 4 + h) * HD + lane * 4]);

    float m0 = -1e30f, m1 = -1e30f, m2 = -1e30f, m3 = -1e30f;
    int key0 = chunk * CHUNK + warp * 64;

    // ---- phase 1: QK scores ----
    #pragma unroll 2
    for (int i = 0; i < 64; i++) {
        int key = key0 + i;
        const float* krow = (key == POS)
            ? &g_k[(b * NKV + kvh) * HD]
            : &cache_k[(((size_t)b * SEQ + key) * NKV + kvh) * HD];
        float4 kv = *reinterpret_cast<const float4*>(&krow[lane * 4]);

        float s0 = qv[0].x * kv.x + qv[0].y * kv.y + qv[0].z * kv.z + qv[0].w * kv.w;
        float s1 = qv[1].x * kv.x + qv[1].y * kv.y + qv[1].z * kv.z + qv[1].w * kv.w;
        float s2 = qv[2].x * kv.x + qv[2].y * kv.y + qv[2].z * kv.z + qv[2].w * kv.w;
        float s3 = qv[3].x * kv.x + qv[3].y * kv.y + qv[3].z * kv.z + qv[3].w * kv.w;
        #pragma unroll
        for (int off = 16; off; off >>= 1) {
            s0 += __shfl_xor_sync(0xffffffffu, s0, off);
            s1 += __shfl_xor_sync(0xffffffffu, s1, off);
            s2 += __shfl_xor_sync(0xffffffffu, s2, off);
            s3 += __shfl_xor_sync(0xffffffffu, s3, off);
        }
        m0 = fmaxf(m0, s0); m1 = fmaxf(m1, s1);
        m2 = fmaxf(m2, s2); m3 = fmaxf(m3, s3);
        if (lane < 4) {
            float sv = (lane == 0) ? s0 : (lane == 1) ? s1 : (lane == 2) ? s2 : s3;
            sc[lane][warp * 64 + i] = sv;
        }
    }
    if (lane < 4)
        wm[warp][lane] = (lane == 0) ? m0 : (lane == 1) ? m1 : (lane == 2) ? m2 : m3;
    __syncthreads();

    if (tid < 4) {
        float m = wm[0][tid];
        #pragma unroll
        for (int w = 1; w < 8; w++) m = fmaxf(m, wm[w][tid]);
        mfin[tid] = m;
    }
    __syncthreads();

    // ---- phase 2: softmax numerator + l ----
    {
        int h = tid >> 6;
        float m = mfin[h];
        float lsum = 0.f;
        #pragma unroll
        for (int j = 0; j < 8; j++) {
            int kk = (tid & 63) * 8 + j;
            float p = __expf(sc[h][kk] - m);
            sc[h][kk] = p;
            lsum += p;
        }
        #pragma unroll
        for (int off = 16; off; off >>= 1)
            lsum += __shfl_xor_sync(0xffffffffu, lsum, off);
        if (lane == 0) atomicAdd(&lfin[h], lsum);
    }
    __syncthreads();

    // ---- phase 3: P @ V ----
    float4 a0 = make_float4(0, 0, 0, 0), a1 = a0, a2 = a0, a3 = a0;
    #pragma unroll 2
    for (int i = 0; i < 64; i++) {
        int key = key0 + i;
        const float* vrow = (key == POS)
            ? &g_v[(b * NKV + kvh) * HD]
            : &cache_v[(((size_t)b * SEQ + key) * NKV + kvh) * HD];
        float4 vv = *reinterpret_cast<const float4*>(&vrow[lane * 4]);
        int kl = warp * 64 + i;
        float p0 = sc[0][kl], p1 = sc[1][kl], p2 = sc[2][kl], p3 = sc[3][kl];
        a0.x += p0 * vv.x; a0.y += p0 * vv.y; a0.z += p0 * vv.z; a0.w += p0 * vv.w;
        a1.x += p1 * vv.x; a1.y += p1 * vv.y; a1.z += p1 * vv.z; a1.w += p1 * vv.w;
        a2.x += p2 * vv.x; a2.y += p2 * vv.y; a2.z += p2 * vv.z; a2.w += p2 * vv.w;
        a3.x += p3 * vv.x; a3.y += p3 * vv.y; a3.z += p3 * vv.z; a3.w += p3 * vv.w;
    }
    ored[warp][0][lane] = a0;
    ored[warp][1][lane] = a1;
    ored[warp][2][lane] = a2;
    ored[warp][3][lane] = a3;
    __syncthreads();

    const float* of = reinterpret_cast<const float*>(ored);
    int pbase = ((b * NKV + kvh) * NCHUNK + chunk) * 4;
    #pragma unroll
    for (int r = 0; r < 2; r++) {
        int o  = tid + r * 256;
        int hh = o >> 7;
        int d  = o & 127;
        float sum = 0.f;
        #pragma unroll
        for (int w = 0; w < 8; w++)
            sum += of[(w * 4 + hh) * HD + d];
        g_Opart[(size_t)(pbase + hh) * HD + d] = sum;
    }
    if (tid < 4) {
        g_m[pbase + tid] = mfin[tid];
        g_l[pbase + tid] = lfin[tid];
    }
}

// ---------------- split-softmax combine -> g_at2 (pair-major) ----------------
__global__ void __launch_bounds__(128) combine_kernel()
{
    int kvh = blockIdx.x;
    int b   = blockIdx.y;
    int d   = threadIdx.x;

    #pragma unroll
    for (int h = 0; h < 4; h++) {
        int base = ((b * NKV + kvh) * NCHUNK) * 4 + h;   // + c*4
        float mstar = -1e30f;
        #pragma unroll
        for (int c = 0; c < NCHUNK; c++) mstar = fmaxf(mstar, g_m[base + c * 4]);
        float num = 0.f, den = 0.f;
        #pragma unroll
        for (int c = 0; c < NCHUNK; c++) {
            float w = __expf(g_m[base + c * 4] - mstar);
            den += g_l[base + c * 4] * w;
            num += g_Opart[(size_t)(base + c * 4) * HD + d] * w;
        }
        int e = (kvh * 4 + h) * HD + d;
        g_at2[(b >> 1) * (DIM * 2) + e * 2 + (b & 1)] = num / den;
    }
}

// ---------------- launcher ----------------
extern "C" void kernel_launch(void* const* d_in, const int* in_sizes, int n_in,
                              void* d_out, int out_size)
{
    (void)in_sizes; (void)n_in; (void)out_size;
    const float* x  = (const float*)d_in[0];
    const float* wq = (const float*)d_in[1];
    const float* wk = (const float*)d_in[2];
    const float* wv = (const float*)d_in[3];
    const float* wo = (const float*)d_in[4];
    const float* ck = (const float*)d_in[5];
    const float* cv = (const float*)d_in[6];
    const float* fc = (const float*)d_in[7];
    const float* fs = (const float*)d_in[8];
    float* out = (float*)d_out;

    transpose_x_kernel<<<256, 256>>>(x);
    qkv_gemm_kernel<<<192, 256>>>(wq, wk, wv);
    rope_kernel<<<160, 256>>>(fc, fs);
    attn_partial_kernel<<<dim3(NCHUNK, NKV, BSZ), 256>>>(ck, cv);
    combine_kernel<<<dim3(NKV, BSZ), 128>>>();
    wo_gemm_kernel<<<128, 256>>>(wo, out);
}

// round 5
// speedup vs baseline: 2.7308x; 1.5127x over previous
#include <cuda_runtime.h>
#include <cuda_bf16.h>
#include <math.h>

// Problem constants (fixed by the reference)
#define BSZ     16
#define DIM     4096
#define NH      32
#define NKV     8
#define HD      128
#define SEQ     4096
#define POS     4095
#define NCHUNK  8
#define CHUNK   512   // SEQ / NCHUNK
#define SUBK    64    // keys per staged sub-tile
#define NSUB    (CHUNK / SUBK)   // 8
#define KROW    132   // padded floats per K/V row (33 float4, 16B aligned)

#define KVROWS  (NKV * HD)       // 1024 rows in wk / wv

// GEMM tiling
#define KC2     128
#define NK2     (DIM / KC2)      // 32

// ---------------- scratch (static __device__, no allocation) ----------------
__device__ float g_xt2[8 * DIM * 2];                    // x pair-major [pair][d][2]
__device__ float g_q[BSZ * NH * HD];                    // [b][h][d]
__device__ float g_k[BSZ * KVROWS];                     // [b][kvh][d]
__device__ float g_v[BSZ * KVROWS];                     // [b][kvh][d]
__device__ float g_at2[8 * DIM * 2];                    // attn out pair-major [pair][e][2]
__device__ float g_Opart[BSZ * NKV * NCHUNK * 4 * HD];  // [b][kvh][chunk][hloc][d]
__device__ float g_m[BSZ * NKV * NCHUNK * 4];
__device__ float g_l[BSZ * NKV * NCHUNK * 4];

// ---------------- f32x2 helpers (sm_103a packed fp32) ----------------
__device__ __forceinline__ unsigned long long pack2(float a, float b) {
    unsigned long long r;
    asm("mov.b64 %0, {%1, %2};" : "=l"(r) : "f"(a), "f"(b));
    return r;
}
__device__ __forceinline__ void unpack2(unsigned long long v, float& a, float& b) {
    asm("mov.b64 {%0, %1}, %2;" : "=f"(a), "=f"(b) : "l"(v));
}
__device__ __forceinline__ unsigned long long fma2(unsigned long long a,
                                                   unsigned long long b,
                                                   unsigned long long c) {
    unsigned long long d;
    asm("fma.rn.f32x2 %0, %1, %2, %3;" : "=l"(d) : "l"(a), "l"(b), "l"(c));
    return d;
}
__device__ __forceinline__ unsigned long long add2(unsigned long long a,
                                                   unsigned long long b) {
    unsigned long long d;
    asm("add.rn.f32x2 %0, %1, %2;" : "=l"(d) : "l"(a), "l"(b));
    return d;
}

// ---------------- cp.async helpers ----------------
__device__ __forceinline__ void cp_async16(void* smem, const void* gmem) {
    unsigned sa = (unsigned)__cvta_generic_to_shared(smem);
    asm volatile("cp.async.ca.shared.global [%0], [%1], 16;" :: "r"(sa), "l"(gmem) : "memory");
}
__device__ __forceinline__ void cp_commit() {
    asm volatile("cp.async.commit_group;" ::: "memory");
}
__device__ __forceinline__ void cp_wait1() {
    asm volatile("cp.async.wait_group 1;" ::: "memory");
}
__device__ __forceinline__ void cp_wait0() {
    asm volatile("cp.async.wait_group 0;" ::: "memory");
}

// ---------------- x transpose: x[b][d] -> g_xt2 pair-major ----------------
__global__ void __launch_bounds__(256) transpose_x_kernel(const float* __restrict__ x)
{
    int gid = blockIdx.x * 256 + threadIdx.x;   // gid = b*4096 + d
    int b = gid >> 12;
    int d = gid & 4095;
    g_xt2[(b >> 1) * (DIM * 2) + d * 2 + (b & 1)] = x[gid];
}

// ---------------- GEMM core (cp.async staged W + x, f32x2 math) ----------------
// Per block: 32 rows (8 warps x 4), all 16 batches, K streamed in 128-chunks.
__device__ __forceinline__ void gemm_core(const float* __restrict__ Wblk,  // block row0 applied
                                          const float* __restrict__ xt2,  // pair-major [8][DIM][2]
                                          float* __restrict__ dst,        // [16][dsz]
                                          int dsz, int drow0)
{
    __shared__ __align__(16) float ws[2][32][KC2];      // 32 KB
    __shared__ __align__(16) float xs[2][8][KC2][2];    // 16 KB

    const int tid  = threadIdx.x;
    const int warp = tid >> 5;
    const int lane = tid & 31;

    unsigned long long acc[32];
    #pragma unroll
    for (int i = 0; i < 32; i++) acc[i] = 0ULL;

    auto stage = [&](int c, int bufi) {
        #pragma unroll
        for (int j = 0; j < 4; j++) {           // W: 32 rows x 32 float4
            int idx = tid + j * 256;
            int row = idx >> 5, f4 = idx & 31;
            cp_async16(&ws[bufi][row][f4 * 4],
                       Wblk + (size_t)row * DIM + c * KC2 + f4 * 4);
        }
        #pragma unroll
        for (int j = 0; j < 2; j++) {           // x: 8 planes x 64 float4
            int idx = tid + j * 256;
            int p = idx >> 6, f4 = idx & 63;
            cp_async16(&xs[bufi][p][0][0] + f4 * 4,
                       xt2 + p * (DIM * 2) + c * (KC2 * 2) + f4 * 4);
        }
        cp_commit();
    };

    stage(0, 0);
    stage(1, 1);

    for (int c = 0; c < NK2; c++) {
        if (c < NK2 - 1) cp_wait1(); else cp_wait0();
        __syncthreads();
        const int cb = c & 1;

        #pragma unroll
        for (int s = 0; s < KC2 / 32; s++) {
            int kl = s * 32 + lane;
            float w0 = ws[cb][warp * 4 + 0][kl];
            float w1 = ws[cb][warp * 4 + 1][kl];
            float w2 = ws[cb][warp * 4 + 2][kl];
            float w3 = ws[cb][warp * 4 + 3][kl];

            unsigned long long xp[8];
            #pragma unroll
            for (int p = 0; p < 8; p++)
                xp[p] = *reinterpret_cast<const unsigned long long*>(&xs[cb][p][kl][0]);

            unsigned long long wv;
            wv = pack2(w0, w0);
            #pragma unroll
            for (int p = 0; p < 8; p++) acc[0 * 8 + p] = fma2(wv, xp[p], acc[0 * 8 + p]);
            wv = pack2(w1, w1);
            #pragma unroll
            for (int p = 0; p < 8; p++) acc[1 * 8 + p] = fma2(wv, xp[p], acc[1 * 8 + p]);
            wv = pack2(w2, w2);
            #pragma unroll
            for (int p = 0; p < 8; p++) acc[2 * 8 + p] = fma2(wv, xp[p], acc[2 * 8 + p]);
            wv = pack2(w3, w3);
            #pragma unroll
            for (int p = 0; p < 8; p++) acc[3 * 8 + p] = fma2(wv, xp[p], acc[3 * 8 + p]);
        }
        __syncthreads();
        if (c + 2 < NK2) stage(c + 2, cb);
    }

    // butterfly reduce across lanes (k partials)
    #pragma unroll
    for (int off = 16; off; off >>= 1) {
        #pragma unroll
        for (int i = 0; i < 32; i++)
            acc[i] = add2(acc[i], __shfl_xor_sync(0xffffffffu, acc[i], off));
    }

    if (lane < 16) {
        int p = lane >> 1, h = lane & 1;
        #pragma unroll
        for (int r = 0; r < 4; r++) {
            float lo, hi;
            unpack2(acc[r * 8 + p], lo, hi);
            dst[(size_t)lane * dsz + drow0 + warp * 4 + r] = h ? hi : lo;
        }
    }
}

// Fused QKV GEMM over 6144 rows
__global__ void __launch_bounds__(256) qkv_gemm_kernel(const float* __restrict__ wq,
                                                       const float* __restrict__ wk,
                                                       const float* __restrict__ wv)
{
    int row0 = blockIdx.x * 32;
    const float* Wblk; float* dst; int dsz, drow0;
    if (row0 < 4096) {
        Wblk = wq + (size_t)row0 * DIM;          dst = g_q; dsz = 4096;   drow0 = row0;
    } else if (row0 < 4096 + KVROWS) {
        Wblk = wk + (size_t)(row0 - 4096) * DIM; dst = g_k; dsz = KVROWS; drow0 = row0 - 4096;
    } else {
        Wblk = wv + (size_t)(row0 - 4096 - KVROWS) * DIM;
        dst = g_v; dsz = KVROWS; drow0 = row0 - 4096 - KVROWS;
    }
    gemm_core(Wblk, g_xt2, dst, dsz, drow0);
}

__global__ void __launch_bounds__(256) wo_gemm_kernel(const float* __restrict__ wo,
                                                      float* __restrict__ out)
{
    int row0 = blockIdx.x * 32;
    gemm_core(wo + (size_t)row0 * DIM, g_at2, out, 4096, row0);
}

// ---------------- RoPE (+ 1/sqrt(HD) scale folded into q) ----------------
__global__ void __launch_bounds__(256) rope_kernel(const float* __restrict__ fcos,
                                                   const float* __restrict__ fsin)
{
    int id = blockIdx.x * 256 + threadIdx.x;
    const float scale = 0.08838834764831845f;   // 1/sqrt(128)
    if (id < BSZ * NH * (HD / 2)) {
        int i = id & 63;
        float c = fcos[i], s = fsin[i];
        float a  = g_q[2 * id];
        float bb = g_q[2 * id + 1];
        g_q[2 * id]     = (a * c - bb * s) * scale;
        g_q[2 * id + 1] = (a * s + bb * c) * scale;
    } else {
        int kid = id - BSZ * NH * (HD / 2);
        if (kid < BSZ * NKV * (HD / 2)) {
            int i = kid & 63;
            float c = fcos[i], s = fsin[i];
            float a  = g_k[2 * kid];
            float bb = g_k[2 * kid + 1];
            g_k[2 * kid]     = a * c - bb * s;
            g_k[2 * kid + 1] = a * s + bb * c;
        }
    }
}

// ---------------- flash-decoding partial attention (cp.async staged) ----------------
// grid (chunk=8, kvh=8, b=16), 256 threads = 8 warps.
// Dynamic smem: kvbuf[2][SUBK][KROW] + sc[512][4] + ored[8][128]
__global__ void __launch_bounds__(256) attn_partial_kernel(const float* __restrict__ cache_k,
                                                           const float* __restrict__ cache_v)
{
    extern __shared__ __align__(16) float dyn[];
    float* kvbuf = dyn;                         // 2*64*132 = 16896 floats
    float* sc    = dyn + 2 * SUBK * KROW;       // 512*4 = 2048 floats, [key][head]
    float* ored  = sc + CHUNK * 4;              // 8*128 floats, [(half*4+h)][d]

    __shared__ float redm[8][4], redl[8][4], mfin[4], lfin[4];

    const int chunk = blockIdx.x;
    const int kvh   = blockIdx.y;
    const int b     = blockIdx.z;
    const int tid   = threadIdx.x;
    const int warp  = tid >> 5;
    const int lane  = tid & 31;
    const int g     = lane >> 3;     // key group within warp iter
    const int s     = lane & 7;      // dim slice

    const size_t rowstride = (size_t)NKV * HD;
    const float* kbase = cache_k + (size_t)b * SEQ * rowstride + (size_t)kvh * HD
                         + (size_t)(chunk * CHUNK) * rowstride;
    const float* vbase = cache_v + (size_t)b * SEQ * rowstride + (size_t)kvh * HD
                         + (size_t)(chunk * CHUNK) * rowstride;

    // q registers: head h, slice dims 4*(s+8j)..+3, packed f32x2 pairs
    ulonglong2 qr[4][4];
    #pragma unroll
    for (int h = 0; h < 4; h++) {
        const float* qp = &g_q[((b * NH) + kvh * 4 + h) * HD];
        #pragma unroll
        for (int j = 0; j < 4; j++)
            qr[h][j] = *reinterpret_cast<const ulonglong2*>(&qp[4 * (s + 8 * j)]);
    }

    auto stage = [&](const float* src, int t, int bufi) {
        const float* stile = src + (size_t)(t * SUBK) * rowstride;
        float* dstb = kvbuf + bufi * (SUBK * KROW);
        #pragma unroll
        for (int j = 0; j < 8; j++) {      // 64 rows x 32 float4
            int idx = tid + j * 256;
            int row = idx >> 5, f4 = idx & 31;
            cp_async16(dstb + row * KROW + f4 * 4,
                       stile + (size_t)row * rowstride + f4 * 4);
        }
        cp_commit();
    };

    const bool dofix = (chunk == NCHUNK - 1);

    // ================= phase 1: QK scores =================
    stage(kbase, 0, 0);
    stage(kbase, 1, 1);

    for (int t = 0; t < NSUB; t++) {
        if (t < NSUB - 1) cp_wait1(); else cp_wait0();
        __syncthreads();
        float* buf = kvbuf + (t & 1) * (SUBK * KROW);

        if (dofix && t == NSUB - 1) {       // substitute key POS with rope'd k
            if (warp == 0)
                reinterpret_cast<float4*>(buf + 63 * KROW)[lane] =
                    reinterpret_cast<const float4*>(&g_k[(b * NKV + kvh) * HD])[lane];
            __syncthreads();
        }

        #pragma unroll
        for (int it = 0; it < 2; it++) {
            int klocal = warp * 8 + it * 4 + g;
            const ulonglong2* krow = reinterpret_cast<const ulonglong2*>(buf + klocal * KROW);
            ulonglong2 k0 = krow[s];
            ulonglong2 k1 = krow[s + 8];
            ulonglong2 k2 = krow[s + 16];
            ulonglong2 k3 = krow[s + 24];

            float sv0, sv1, sv2, sv3;
            #pragma unroll
            for (int h = 0; h < 4; h++) {
                unsigned long long a = fma2(qr[h][0].x, k0.x, 0ULL);
                a = fma2(qr[h][0].y, k0.y, a);
                a = fma2(qr[h][1].x, k1.x, a);
                a = fma2(qr[h][1].y, k1.y, a);
                a = fma2(qr[h][2].x, k2.x, a);
                a = fma2(qr[h][2].y, k2.y, a);
                a = fma2(qr[h][3].x, k3.x, a);
                a = fma2(qr[h][3].y, k3.y, a);
                float lo, hi; unpack2(a, lo, hi);
                float sum = lo + hi;
                sum += __shfl_xor_sync(0xffffffffu, sum, 1);
                sum += __shfl_xor_sync(0xffffffffu, sum, 2);
                sum += __shfl_xor_sync(0xffffffffu, sum, 4);
                if (h == 0) sv0 = sum; else if (h == 1) sv1 = sum;
                else if (h == 2) sv2 = sum; else sv3 = sum;
            }
            if (s < 4) {
                float o = (s == 0) ? sv0 : (s == 1) ? sv1 : (s == 2) ? sv2 : sv3;
                sc[(t * SUBK + klocal) * 4 + s] = o;
            }
        }
        __syncthreads();
        if (t + 2 < NSUB) stage(kbase, t + 2, t & 1);
    }

    // ================= V prologue (overlaps softmax) =================
    stage(vbase, 0, 0);
    stage(vbase, 1, 1);

    // ================= phase 2: softmax =================
    {
        float4* sc4 = reinterpret_cast<float4*>(sc);
        float4 aa = sc4[tid];
        float4 bb = sc4[tid + 256];
        float mx0 = fmaxf(aa.x, bb.x), mx1 = fmaxf(aa.y, bb.y);
        float mx2 = fmaxf(aa.z, bb.z), mx3 = fmaxf(aa.w, bb.w);
        #pragma unroll
        for (int off = 16; off; off >>= 1) {
            mx0 = fmaxf(mx0, __shfl_xor_sync(0xffffffffu, mx0, off));
            mx1 = fmaxf(mx1, __shfl_xor_sync(0xffffffffu, mx1, off));
            mx2 = fmaxf(mx2, __shfl_xor_sync(0xffffffffu, mx2, off));
            mx3 = fmaxf(mx3, __shfl_xor_sync(0xffffffffu, mx3, off));
        }
        if (lane == 0) { redm[warp][0] = mx0; redm[warp][1] = mx1;
                         redm[warp][2] = mx2; redm[warp][3] = mx3; }
        __syncthreads();
        if (tid < 4) {
            float m = redm[0][tid];
            #pragma unroll
            for (int w = 1; w < 8; w++) m = fmaxf(m, redm[w][tid]);
            mfin[tid] = m;
        }
        __syncthreads();
        float m0 = mfin[0], m1 = mfin[1], m2 = mfin[2], m3 = mfin[3];
        aa.x = __expf(aa.x - m0); aa.y = __expf(aa.y - m1);
        aa.z = __expf(aa.z - m2); aa.w = __expf(aa.w - m3);
        bb.x = __expf(bb.x - m0); bb.y = __expf(bb.y - m1);
        bb.z = __expf(bb.z - m2); bb.w = __expf(bb.w - m3);
        sc4[tid] = aa;
        sc4[tid + 256] = bb;
        float l0 = aa.x + bb.x, l1 = aa.y + bb.y, l2 = aa.z + bb.z, l3 = aa.w + bb.w;
        #pragma unroll
        for (int off = 16; off; off >>= 1) {
            l0 += __shfl_xor_sync(0xffffffffu, l0, off);
            l1 += __shfl_xor_sync(0xffffffffu, l1, off);
            l2 += __shfl_xor_sync(0xffffffffu, l2, off);
            l3 += __shfl_xor_sync(0xffffffffu, l3, off);
        }
        if (lane == 0) { redl[warp][0] = l0; redl[warp][1] = l1;
                         redl[warp][2] = l2; redl[warp][3] = l3; }
        __syncthreads();
        if (tid < 4) {
            float l = 0.f;
            #pragma unroll
            for (int w = 0; w < 8; w++) l += redl[w][tid];
            lfin[tid] = l;
        }
    }

    // ================= phase 3: P @ V =================
    const int vh    = warp & 3;      // head
    const int vhalf = warp >> 2;     // key half within sub-tile
    unsigned long long vacc0 = 0ULL, vacc1 = 0ULL;

    for (int t = 0; t < NSUB; t++) {
        if (t < NSUB - 1) cp_wait1(); else cp_wait0();
        __syncthreads();
        float* buf = kvbuf + (t & 1) * (SUBK * KROW);

        if (dofix && t == NSUB - 1) {       // substitute value POS with new v
            if (warp == 0)
                reinterpret_cast<float4*>(buf + 63 * KROW)[lane] =
                    reinterpret_cast<const float4*>(&g_v[(b * NKV + kvh) * HD])[lane];
            __syncthreads();
        }

        #pragma unroll 4
        for (int kk = 0; kk < 32; kk++) {
            int klocal = vhalf * 32 + kk;
            ulonglong2 vv = reinterpret_cast<const ulonglong2*>(buf + klocal * KROW)[lane];
            float p = sc[(t * SUBK + klocal) * 4 + vh];
            unsigned long long pp = pack2(p, p);
            vacc0 = fma2(pp, vv.x, vacc0);
            vacc1 = fma2(pp, vv.y, vacc1);
        }
        __syncthreads();
        if (t + 2 < NSUB) stage(vbase, t + 2, t & 1);
    }

    // epilogue: combine key halves, write partials
    {
        float o0, o1, o2, o3;
        unpack2(vacc0, o0, o1);
        unpack2(vacc1, o2, o3);
        reinterpret_cast<float4*>(ored + (vhalf * 4 + vh) * HD)[lane] =
            make_float4(o0, o1, o2, o3);
    }
    __syncthreads();

    int pbase = ((b * NKV + kvh) * NCHUNK + chunk) * 4;
    #pragma unroll
    for (int r = 0; r < 2; r++) {
        int idx = tid + r * 256;
        int h = idx >> 7, d = idx & 127;
        g_Opart[(size_t)(pbase + h) * HD + d] = ored[h * HD + d] + ored[(4 + h) * HD + d];
    }
    if (tid < 4) {
        g_m[pbase + tid] = mfin[tid];
        g_l[pbase + tid] = lfin[tid];
    }
}

// ---------------- split-softmax combine -> g_at2 (pair-major) ----------------
__global__ void __launch_bounds__(128) combine_kernel()
{
    int kvh = blockIdx.x;
    int b   = blockIdx.y;
    int d   = threadIdx.x;

    #pragma unroll
    for (int h = 0; h < 4; h++) {
        int base = ((b * NKV + kvh) * NCHUNK) * 4 + h;   // + c*4
        float mstar = -1e30f;
        #pragma unroll
        for (int c = 0; c < NCHUNK; c++) mstar = fmaxf(mstar, g_m[base + c * 4]);
        float num = 0.f, den = 0.f;
        #pragma unroll
        for (int c = 0; c < NCHUNK; c++) {
            float w = __expf(g_m[base + c * 4] - mstar);
            den += g_l[base + c * 4] * w;
            num += g_Opart[(size_t)(base + c * 4) * HD + d] * w;
        }
        int e = (kvh * 4 + h) * HD + d;
        g_at2[(b >> 1) * (DIM * 2) + e * 2 + (b & 1)] = num / den;
    }
}

// ---------------- launcher ----------------
#define ATTN_SMEM ((2 * SUBK * KROW + CHUNK * 4 + 8 * HD) * (int)sizeof(float))

extern "C" void kernel_launch(void* const* d_in, const int* in_sizes, int n_in,
                              void* d_out, int out_size)
{
    (void)in_sizes; (void)n_in; (void)out_size;
    const float* x  = (const float*)d_in[0];
    const float* wq = (const float*)d_in[1];
    const float* wk = (const float*)d_in[2];
    const float* wv = (const float*)d_in[3];
    const float* wo = (const float*)d_in[4];
    const float* ck = (const float*)d_in[5];
    const float* cv = (const float*)d_in[6];
    const float* fc = (const float*)d_in[7];
    const float* fs = (const float*)d_in[8];
    float* out = (float*)d_out;

    cudaFuncSetAttribute(attn_partial_kernel,
                         cudaFuncAttributeMaxDynamicSharedMemorySize, ATTN_SMEM);

    transpose_x_kernel<<<256, 256>>>(x);
    qkv_gemm_kernel<<<192, 256>>>(wq, wk, wv);
    rope_kernel<<<160, 256>>>(fc, fs);
    attn_partial_kernel<<<dim3(NCHUNK, NKV, BSZ), 256, ATTN_SMEM>>>(ck, cv);
    combine_kernel<<<dim3(NKV, BSZ), 128>>>();
    wo_gemm_kernel<<<128, 256>>>(wo, out);
}